// round 4
// baseline (speedup 1.0000x reference)
#include <cuda_runtime.h>
#include <cstdint>

#define NODES   50000
#define INDIM   128
#define HH      256     // HEADS*HIDDEN
#define HEADS   4
#define HID     64
#define EPSV    1e-5f
#define NEG     0.2f

// -------- device scratch (no allocation allowed) --------
__device__ float g_hl [NODES * HH];   // linear features (reused both layers)
__device__ float g_h2 [NODES * HH];   // post-BN2+ReLU features
__device__ float g_agg[NODES * HH];   // weighted-message accumulator (reused)
__device__ float g_asrc[NODES * HEADS];
__device__ float g_adst[NODES * HEADS];
__device__ float g_denom[NODES * HEADS];
__device__ float g_sums[512];         // [0:256) sum, [256:512) sumsq
__device__ float g_scale[256];
__device__ float g_shift[256];
__device__ float g_mean[256];
__device__ float g_rowbias[256];

// ---------------- utility kernels ----------------
__global__ void k_clear(float* __restrict__ p, int n) {
    int i = blockIdx.x * blockDim.x + threadIdx.x;
    if (i < n) p[i] = 0.f;
}

// column stats: blockDim == C, each block strides over rows (coalesced)
__global__ void k_colstats(const float* __restrict__ x, int n, int C,
                           float* __restrict__ sums, float* __restrict__ sumsq) {
    int c = threadIdx.x;
    float s = 0.f, s2 = 0.f;
    for (int r = blockIdx.x; r < n; r += gridDim.x) {
        float v = x[(size_t)r * C + c];
        s += v; s2 += v * v;
    }
    atomicAdd(&sums[c], s);
    atomicAdd(&sumsq[c], s2);
}

// finalize BN stats. fold=1: produce scale + shift (for GEMM folding)
// fold=0: produce scale + mean (for explicit normalize)
__global__ void k_bnfinal(const float* __restrict__ gamma, const float* __restrict__ beta,
                          int C, int n, int fold) {
    int c = threadIdx.x;
    if (c >= C) return;
    float mean = g_sums[c] / (float)n;
    float var  = g_sums[256 + c] / (float)n - mean * mean;
    float sc   = rsqrtf(var + EPSV) * gamma[c];
    g_scale[c] = sc;
    if (fold) g_shift[c] = beta[c] - mean * sc;
    else      g_mean[c]  = mean;
}

// rowbias[j] = sum_k shift[k] * W[k, j]   (BN fold constant term)
__global__ void k_rowbias(const float* __restrict__ W, int K) {
    int j = threadIdx.x;
    float s = 0.f;
    for (int k = 0; k < K; k++) s += g_shift[k] * W[(size_t)k * HH + j];
    g_rowbias[j] = s;
}

// ---------------- SGEMM: C[M,256] = A[M,K] @ (colscale ∘ B)[K,256] + rowbias ----------------
__global__ __launch_bounds__(256)
void k_sgemm(const float* __restrict__ A, const float* __restrict__ B, float* __restrict__ C,
             int M, int K, const float* __restrict__ colscale, const float* __restrict__ rowbias) {
    const int BM = 64, BN = 64, BK = 16;
    __shared__ float As[BK][BM];
    __shared__ float Bs[BK][BN];
    int tx = threadIdx.x & 15, ty = threadIdx.x >> 4;
    int rowBase = blockIdx.y * BM, colBase = blockIdx.x * BN;
    float acc[4][4] = {};
    for (int k0 = 0; k0 < K; k0 += BK) {
        for (int i = threadIdx.x; i < BM * BK; i += 256) {
            int r = i >> 4, kk = i & 15;
            int gr = rowBase + r;
            As[kk][r] = (gr < M) ? A[(size_t)gr * K + k0 + kk] : 0.f;
        }
        for (int i = threadIdx.x; i < BK * BN; i += 256) {
            int kk = i >> 6, c = i & 63;
            float v = B[(size_t)(k0 + kk) * HH + colBase + c];
            if (colscale) v *= colscale[k0 + kk];
            Bs[kk][c] = v;
        }
        __syncthreads();
#pragma unroll
        for (int kk = 0; kk < BK; kk++) {
            float a[4], b[4];
#pragma unroll
            for (int m = 0; m < 4; m++) a[m] = As[kk][ty * 4 + m];
#pragma unroll
            for (int n = 0; n < 4; n++) b[n] = Bs[kk][tx * 4 + n];
#pragma unroll
            for (int m = 0; m < 4; m++)
#pragma unroll
                for (int n = 0; n < 4; n++) acc[m][n] += a[m] * b[n];
        }
        __syncthreads();
    }
#pragma unroll
    for (int m = 0; m < 4; m++) {
        int gr = rowBase + ty * 4 + m;
        if (gr < M) {
#pragma unroll
            for (int n = 0; n < 4; n++) {
                int gc = colBase + tx * 4 + n;
                float v = acc[m][n];
                if (rowbias) v += rowbias[gc];
                C[(size_t)gr * HH + gc] = v;
            }
        }
    }
}

// ---------------- attention scores: warp per node ----------------
__global__ void k_attn(const float* __restrict__ hl, const float* __restrict__ atts,
                       const float* __restrict__ attd, int n) {
    int w = (blockIdx.x * blockDim.x + threadIdx.x) >> 5;
    int lane = threadIdx.x & 31;
    if (w >= n) return;
    const float* row = hl + (size_t)w * HH;
    float ss[HEADS] = {}, dd[HEADS] = {};
#pragma unroll
    for (int h = 0; h < HEADS; h++) {
#pragma unroll
        for (int j = 0; j < 2; j++) {
            int c = h * 64 + j * 32 + lane;
            float v = row[c];
            ss[h] += v * atts[c];
            dd[h] += v * attd[c];
        }
    }
#pragma unroll
    for (int off = 16; off; off >>= 1) {
#pragma unroll
        for (int h = 0; h < HEADS; h++) {
            ss[h] += __shfl_xor_sync(0xffffffffu, ss[h], off);
            dd[h] += __shfl_xor_sync(0xffffffffu, dd[h], off);
        }
    }
    if (lane == 0) {
#pragma unroll
        for (int h = 0; h < HEADS; h++) {
            g_asrc[w * HEADS + h] = ss[h];
            g_adst[w * HEADS + h] = dd[h];
        }
    }
}

// ---------------- edge aggregation: warp per edge ----------------
// accumulates exp(e)*hl[src] into g_agg[dst], exp(e) into g_denom[dst]
// (segment softmax w/o max-shift: shift-invariant, logits are O(1))
// NOTE: edge_index is int32 (JAX x64 disabled -> jnp.int64 materializes as int32)
__global__ void k_edgeagg(const int* __restrict__ srcp, const int* __restrict__ dstp,
                          int E, int n) {
    int w = (blockIdx.x * blockDim.x + threadIdx.x) >> 5;
    int lane = threadIdx.x & 31;
    int Et = E + n;
    if (w >= Et) return;
    int s, d;
    if (w < E) { s = srcp[w]; d = dstp[w]; }
    else       { s = d = w - E; }
    float wl = 0.f;
    if (lane < HEADS) {
        float a = g_asrc[s * HEADS + lane] + g_adst[d * HEADS + lane];
        a = (a > 0.f) ? a : NEG * a;
        wl = __expf(a);
        atomicAdd(&g_denom[d * HEADS + lane], wl);
    }
    const float* hr = g_hl + (size_t)s * HH;
    float* orow = g_agg + (size_t)d * HH;
#pragma unroll
    for (int h = 0; h < HEADS; h++) {
        float wh = __shfl_sync(0xffffffffu, wl, h);
        int c = h * 64 + lane;
        atomicAdd(&orow[c],      wh * hr[c]);
        atomicAdd(&orow[c + 32], wh * hr[c + 32]);
    }
}

// layer-1 finalize: agg = agg/denom + bias1 (in place; concat layout already flat)
__global__ void k_final1(const float* __restrict__ bias, int n) {
    size_t i = (size_t)blockIdx.x * blockDim.x + threadIdx.x;
    if (i >= (size_t)n * HH) return;
    int node = (int)(i >> 8);
    int c = (int)(i & 255);
    g_agg[i] = g_agg[i] / g_denom[node * HEADS + (c >> 6)] + bias[c];
}

// BN2 normalize + ReLU -> g_h2
__global__ void k_bnrelu(const float* __restrict__ beta, int n) {
    size_t i = (size_t)blockIdx.x * blockDim.x + threadIdx.x;
    if (i >= (size_t)n * HH) return;
    int c = (int)(i & 255);
    float v = (g_agg[i] - g_mean[c]) * g_scale[c] + beta[c];
    g_h2[i] = (v > 0.f) ? v : 0.f;
}

// layer-2 finalize: out[n,c] = mean_h(agg[n,h,c]/denom[n,h]) + bias2[c]
__global__ void k_final2(const float* __restrict__ bias2, float* __restrict__ out, int n) {
    int i = blockIdx.x * blockDim.x + threadIdx.x;
    if (i >= n * HID) return;
    int node = i >> 6, c = i & 63;
    const float* ar = g_agg + (size_t)node * HH;
    const float* dr = g_denom + node * HEADS;
    float v = 0.f;
#pragma unroll
    for (int h = 0; h < HEADS; h++) v += ar[h * 64 + c] / dr[h];
    out[i] = 0.25f * v + bias2[c];
}

// ---------------- host launcher ----------------
extern "C" void kernel_launch(void* const* d_in, const int* in_sizes, int n_in,
                              void* d_out, int out_size) {
    const float* x        = (const float*)d_in[0];
    const int*   ei       = (const int*)d_in[1];      // int32! (JAX x64 disabled)
    const float* gamma1   = (const float*)d_in[2];
    const float* beta1    = (const float*)d_in[3];
    const float* W1       = (const float*)d_in[4];
    const float* att_src1 = (const float*)d_in[5];
    const float* att_dst1 = (const float*)d_in[6];
    const float* bias1    = (const float*)d_in[7];
    const float* gamma2   = (const float*)d_in[8];
    const float* beta2    = (const float*)d_in[9];
    const float* W2       = (const float*)d_in[10];
    const float* att_src2 = (const float*)d_in[11];
    const float* att_dst2 = (const float*)d_in[12];
    const float* bias2    = (const float*)d_in[13];

    int n = in_sizes[0] / INDIM;
    int E = in_sizes[1] / 2;
    const int* srcp = ei;
    const int* dstp = ei + E;
    float* out = (float*)d_out;

    float *p_hl, *p_h2, *p_agg, *p_denom, *p_sums, *p_scale, *p_rowbias;
    cudaGetSymbolAddress((void**)&p_hl,      g_hl);
    cudaGetSymbolAddress((void**)&p_h2,      g_h2);
    cudaGetSymbolAddress((void**)&p_agg,     g_agg);
    cudaGetSymbolAddress((void**)&p_denom,   g_denom);
    cudaGetSymbolAddress((void**)&p_sums,    g_sums);
    cudaGetSymbolAddress((void**)&p_scale,   g_scale);
    cudaGetSymbolAddress((void**)&p_rowbias, g_rowbias);

    int Et = E + n;
    int featElems = n * HH;
    dim3 gemmGrid(HH / 64, (n + 63) / 64);

    // ---- BN1 (folded into GEMM1) ----
    k_clear<<<2, 256>>>(p_sums, 512);
    k_colstats<<<512, INDIM>>>(x, n, INDIM, p_sums, p_sums + 256);
    k_bnfinal<<<1, INDIM>>>(gamma1, beta1, INDIM, n, 1);
    k_rowbias<<<1, HH>>>(W1, INDIM);

    // ---- GAT1 ----
    k_sgemm<<<gemmGrid, 256>>>(x, W1, p_hl, n, INDIM, p_scale, p_rowbias);
    k_attn<<<(n * 32 + 255) / 256, 256>>>(p_hl, att_src1, att_dst1, n);
    k_clear<<<(n * HEADS + 255) / 256, 256>>>(p_denom, n * HEADS);
    k_clear<<<(featElems + 255) / 256, 256>>>(p_agg, featElems);
    k_edgeagg<<<(Et * 32 + 255) / 256, 256>>>(srcp, dstp, E, n);
    k_final1<<<(featElems + 255) / 256, 256>>>(bias1, n);

    // ---- BN2 + ReLU ----
    k_clear<<<2, 256>>>(p_sums, 512);
    k_colstats<<<512, HH>>>(p_agg, n, HH, p_sums, p_sums + 256);
    k_bnfinal<<<1, HH>>>(gamma2, beta2, HH, n, 0);
    k_bnrelu<<<(featElems + 255) / 256, 256>>>(beta2, n);

    // ---- GAT2 ----
    k_sgemm<<<gemmGrid, 256>>>(p_h2, W2, p_hl, n, HH, nullptr, nullptr);
    k_attn<<<(n * 32 + 255) / 256, 256>>>(p_hl, att_src2, att_dst2, n);
    k_clear<<<(n * HEADS + 255) / 256, 256>>>(p_denom, n * HEADS);
    k_clear<<<(featElems + 255) / 256, 256>>>(p_agg, featElems);
    k_edgeagg<<<(Et * 32 + 255) / 256, 256>>>(srcp, dstp, E, n);
    k_final2<<<(n * HID + 255) / 256, 256>>>(bias2, out, n);
}

// round 7
// speedup vs baseline: 1.2580x; 1.2580x over previous
#include <cuda_runtime.h>
#include <cuda_bf16.h>
#include <cstdint>

#define NODES   50000
#define INDIM   128
#define HH      256     // HEADS*HIDDEN
#define HEADS   4
#define HID     64
#define EPSV    1e-5f
#define NEG     0.2f

// ---------------- PTX helpers (base sm_103-safe: ldmatrix + mma.sync only) ----------------
__device__ __forceinline__ uint32_t smem_to_u32(const void* p) {
    uint32_t a;
    asm("{ .reg .u64 t; cvta.to.shared.u64 t, %1; cvt.u32.u64 %0, t; }" : "=r"(a) : "l"(p));
    return a;
}
#define LDSM_X4(r0, r1, r2, r3, addr) \
    asm volatile("ldmatrix.sync.aligned.m8n8.x4.shared.b16 {%0,%1,%2,%3}, [%4];" \
        : "=r"(r0), "=r"(r1), "=r"(r2), "=r"(r3) : "r"(addr))
#define MMA_BF16(d, a, b) \
    asm volatile("mma.sync.aligned.m16n8k16.row.col.f32.bf16.bf16.f32 " \
        "{%0,%1,%2,%3}, {%4,%5,%6,%7}, {%8,%9}, {%0,%1,%2,%3};" \
        : "+f"((d)[0]), "+f"((d)[1]), "+f"((d)[2]), "+f"((d)[3]) \
        : "r"((a)[0]), "r"((a)[1]), "r"((a)[2]), "r"((a)[3]), "r"((b)[0]), "r"((b)[1]))

// -------- device scratch (no allocation allowed) --------
__device__ float g_hl [NODES * HH];
__device__ float g_h2 [NODES * HH];
__device__ float g_agg[NODES * HH];
__device__ float g_asrc[NODES * HEADS];
__device__ float g_adst[NODES * HEADS];
__device__ float g_denom[NODES * HEADS];
__device__ float g_sums[512];
__device__ float g_scale[256];
__device__ float g_shift[256];
__device__ float g_mean[256];
__device__ float g_rowbias[256];
__device__ uint16_t g_Wt_hi[256 * 256];   // W^T split: bf16 hi   [n][k]
__device__ uint16_t g_Wt_lo[256 * 256];   // bf16 lo residual     [n][k]

// ---------------- utility kernels ----------------
__global__ void k_clear(float* __restrict__ p, int n) {
    int i = blockIdx.x * blockDim.x + threadIdx.x;
    if (i < n) p[i] = 0.f;
}

__global__ void k_colstats(const float* __restrict__ x, int n, int C,
                           float* __restrict__ sums, float* __restrict__ sumsq) {
    int c = threadIdx.x;
    float s = 0.f, s2 = 0.f;
    for (int r = blockIdx.x; r < n; r += gridDim.x) {
        float v = x[(size_t)r * C + c];
        s += v; s2 += v * v;
    }
    atomicAdd(&sums[c], s);
    atomicAdd(&sumsq[c], s2);
}

__global__ void k_bnfinal(const float* __restrict__ gamma, const float* __restrict__ beta,
                          int C, int n, int fold) {
    int c = threadIdx.x;
    if (c >= C) return;
    float mean = g_sums[c] / (float)n;
    float var  = g_sums[256 + c] / (float)n - mean * mean;
    float sc   = rsqrtf(var + EPSV) * gamma[c];
    g_scale[c] = sc;
    if (fold) g_shift[c] = beta[c] - mean * sc;
    else      g_mean[c]  = mean;
}

__global__ void k_rowbias(const float* __restrict__ W, int K) {
    int j = threadIdx.x;
    float s = 0.f;
    for (int k = 0; k < K; k++) s += g_shift[k] * W[(size_t)k * HH + j];
    g_rowbias[j] = s;
}

// ---------------- W pre-transpose + split-bf16 (optionally folding BN colscale) ----------------
__device__ __forceinline__ void splitf(float x, uint16_t& h, uint16_t& l) {
    __nv_bfloat16 bh = __float2bfloat16(x);
    float r = x - __bfloat162float(bh);
    __nv_bfloat16 bl = __float2bfloat16(r);
    h = __bfloat16_as_ushort(bh);
    l = __bfloat16_as_ushort(bl);
}

__global__ void k_prepw(const float* __restrict__ W, int K, const float* __restrict__ colscale) {
    int idx = blockIdx.x * blockDim.x + threadIdx.x;   // idx = n*K + k
    if (idx >= 256 * K) return;
    int n = idx / K, k = idx - n * K;
    float v = W[(size_t)k * 256 + n];
    if (colscale) v *= colscale[k];
    uint16_t h, l;
    splitf(v, h, l);
    g_Wt_hi[idx] = h;
    g_Wt_lo[idx] = l;
}

// ---------------- HMMA GEMM: C[M,256] = A[M,K] @ W (+rowbias), split-bf16 3-term ----------------
// Block 256 thr = 8 warps (4 M x 2 N). Blocktile 128x128, warp tile 32x64 (2x8 m16n8 tiles).
// K chunked by 32; shared rows padded to 40 halfs (80B) -> ldmatrix conflict-free.
#define SPITCH 40

__global__ __launch_bounds__(256)
void k_mmagemm(const float* __restrict__ A, float* __restrict__ C, int M, int K,
               const float* __restrict__ rowbias) {
    __shared__ __align__(16) uint16_t As_hi[128 * SPITCH];
    __shared__ __align__(16) uint16_t As_lo[128 * SPITCH];
    __shared__ __align__(16) uint16_t Bs_hi[128 * SPITCH];
    __shared__ __align__(16) uint16_t Bs_lo[128 * SPITCH];

    const int tid = threadIdx.x, lane = tid & 31, wid = tid >> 5;
    const int warpM = wid >> 1, warpN = wid & 1;
    const int rowBase = blockIdx.y * 128;
    const int colBase = blockIdx.x * 128;

    const uint32_t sAh = smem_to_u32(As_hi), sAl = smem_to_u32(As_lo);
    const uint32_t sBh = smem_to_u32(Bs_hi), sBl = smem_to_u32(Bs_lo);

    float acc[2][8][4] = {};

    for (int k0 = 0; k0 < K; k0 += 32) {
        // ---- stage A chunk: 128 rows x 32 k (fp32 -> hi/lo bf16) ----
        for (int i = tid; i < 128 * 8; i += 256) {
            int r = i >> 3, q = i & 7;
            int gr = rowBase + r;
            float4 v = make_float4(0.f, 0.f, 0.f, 0.f);
            if (gr < M) v = *(const float4*)(A + (size_t)gr * K + k0 + q * 4);
            uint16_t h0, h1, h2, h3, l0, l1, l2, l3;
            splitf(v.x, h0, l0); splitf(v.y, h1, l1);
            splitf(v.z, h2, l2); splitf(v.w, h3, l3);
            int off = r * SPITCH + q * 4;
            uint32_t* ph = (uint32_t*)(As_hi + off);
            uint32_t* pl = (uint32_t*)(As_lo + off);
            ph[0] = (uint32_t)h0 | ((uint32_t)h1 << 16);
            ph[1] = (uint32_t)h2 | ((uint32_t)h3 << 16);
            pl[0] = (uint32_t)l0 | ((uint32_t)l1 << 16);
            pl[1] = (uint32_t)l2 | ((uint32_t)l3 << 16);
        }
        // ---- stage B chunk: 128 n-rows x 32 k (pre-split bf16 from global) ----
        for (int i = tid; i < 128 * 8; i += 256) {
            int n = i >> 3, q = i & 7;
            size_t gofs = (size_t)(colBase + n) * K + k0 + q * 4;
            uint2 vh = *(const uint2*)(g_Wt_hi + gofs);
            uint2 vl = *(const uint2*)(g_Wt_lo + gofs);
            int off = n * SPITCH + q * 4;
            *(uint2*)(Bs_hi + off) = vh;
            *(uint2*)(Bs_lo + off) = vl;
        }
        __syncthreads();

#pragma unroll
        for (int s = 0; s < 2; s++) {
            // A fragments: 2 m-tiles, hi+lo
            uint32_t ah[2][4], al[2][4];
#pragma unroll
            for (int mt = 0; mt < 2; mt++) {
                int rA = warpM * 32 + mt * 16 + (lane & 15);
                int kA = s * 16 + ((lane & 16) ? 8 : 0);
                uint32_t byteOff = (uint32_t)(rA * SPITCH + kA) * 2;
                LDSM_X4(ah[mt][0], ah[mt][1], ah[mt][2], ah[mt][3], sAh + byteOff);
                LDSM_X4(al[mt][0], al[mt][1], al[mt][2], al[mt][3], sAl + byteOff);
            }
            // B fragments: 8 n-tiles (pairs via x4), hi+lo
            uint32_t bh[8][2], bl[8][2];
#pragma unroll
            for (int p = 0; p < 4; p++) {
                int g = lane >> 3;
                int nB = warpN * 64 + p * 16 + ((g & 2) ? 8 : 0) + (lane & 7);
                int kB = s * 16 + ((g & 1) ? 8 : 0);
                uint32_t byteOff = (uint32_t)(nB * SPITCH + kB) * 2;
                LDSM_X4(bh[2*p][0], bh[2*p][1], bh[2*p+1][0], bh[2*p+1][1], sBh + byteOff);
                LDSM_X4(bl[2*p][0], bl[2*p][1], bl[2*p+1][0], bl[2*p+1][1], sBl + byteOff);
            }
#pragma unroll
            for (int mt = 0; mt < 2; mt++)
#pragma unroll
                for (int nt = 0; nt < 8; nt++) {
                    MMA_BF16(acc[mt][nt], ah[mt], bh[nt]);
                    MMA_BF16(acc[mt][nt], ah[mt], bl[nt]);
                    MMA_BF16(acc[mt][nt], al[mt], bh[nt]);
                }
        }
        __syncthreads();
    }

    // ---- epilogue: fragment layout -> global (float2 stores) ----
#pragma unroll
    for (int mt = 0; mt < 2; mt++) {
        int r0 = rowBase + warpM * 32 + mt * 16 + (lane >> 2);
#pragma unroll
        for (int half = 0; half < 2; half++) {
            int row = r0 + half * 8;
            if (row >= M) continue;
#pragma unroll
            for (int nt = 0; nt < 8; nt++) {
                int col = colBase + warpN * 64 + nt * 8 + (lane & 3) * 2;
                float v0 = acc[mt][nt][half * 2];
                float v1 = acc[mt][nt][half * 2 + 1];
                if (rowbias) { v0 += rowbias[col]; v1 += rowbias[col + 1]; }
                *(float2*)(C + (size_t)row * 256 + col) = make_float2(v0, v1);
            }
        }
    }
}

// ---------------- attention scores: warp per node ----------------
__global__ void k_attn(const float* __restrict__ hl, const float* __restrict__ atts,
                       const float* __restrict__ attd, int n) {
    int w = (blockIdx.x * blockDim.x + threadIdx.x) >> 5;
    int lane = threadIdx.x & 31;
    if (w >= n) return;
    const float* row = hl + (size_t)w * HH;
    float ss[HEADS] = {}, dd[HEADS] = {};
#pragma unroll
    for (int h = 0; h < HEADS; h++) {
#pragma unroll
        for (int j = 0; j < 2; j++) {
            int c = h * 64 + j * 32 + lane;
            float v = row[c];
            ss[h] += v * atts[c];
            dd[h] += v * attd[c];
        }
    }
#pragma unroll
    for (int off = 16; off; off >>= 1) {
#pragma unroll
        for (int h = 0; h < HEADS; h++) {
            ss[h] += __shfl_xor_sync(0xffffffffu, ss[h], off);
            dd[h] += __shfl_xor_sync(0xffffffffu, dd[h], off);
        }
    }
    if (lane == 0) {
#pragma unroll
        for (int h = 0; h < HEADS; h++) {
            g_asrc[w * HEADS + h] = ss[h];
            g_adst[w * HEADS + h] = dd[h];
        }
    }
}

// ---------------- edge aggregation: warp per edge (atomic scatter) ----------------
__global__ void k_edgeagg(const int* __restrict__ srcp, const int* __restrict__ dstp,
                          int E, int n) {
    int w = (blockIdx.x * blockDim.x + threadIdx.x) >> 5;
    int lane = threadIdx.x & 31;
    int Et = E + n;
    if (w >= Et) return;
    int s, d;
    if (w < E) { s = srcp[w]; d = dstp[w]; }
    else       { s = d = w - E; }
    float wl = 0.f;
    if (lane < HEADS) {
        float a = g_asrc[s * HEADS + lane] + g_adst[d * HEADS + lane];
        a = (a > 0.f) ? a : NEG * a;
        wl = __expf(a);
        atomicAdd(&g_denom[d * HEADS + lane], wl);
    }
    const float* hr = g_hl + (size_t)s * HH;
    float* orow = g_agg + (size_t)d * HH;
#pragma unroll
    for (int h = 0; h < HEADS; h++) {
        float wh = __shfl_sync(0xffffffffu, wl, h);
        int c = h * 64 + lane;
        atomicAdd(&orow[c],      wh * hr[c]);
        atomicAdd(&orow[c + 32], wh * hr[c + 32]);
    }
}

__global__ void k_final1(const float* __restrict__ bias, int n) {
    size_t i = (size_t)blockIdx.x * blockDim.x + threadIdx.x;
    if (i >= (size_t)n * HH) return;
    int node = (int)(i >> 8);
    int c = (int)(i & 255);
    g_agg[i] = g_agg[i] / g_denom[node * HEADS + (c >> 6)] + bias[c];
}

__global__ void k_bnrelu(const float* __restrict__ beta, int n) {
    size_t i = (size_t)blockIdx.x * blockDim.x + threadIdx.x;
    if (i >= (size_t)n * HH) return;
    int c = (int)(i & 255);
    float v = (g_agg[i] - g_mean[c]) * g_scale[c] + beta[c];
    g_h2[i] = (v > 0.f) ? v : 0.f;
}

__global__ void k_final2(const float* __restrict__ bias2, float* __restrict__ out, int n) {
    int i = blockIdx.x * blockDim.x + threadIdx.x;
    if (i >= n * HID) return;
    int node = i >> 6, c = i & 63;
    const float* ar = g_agg + (size_t)node * HH;
    const float* dr = g_denom + node * HEADS;
    float v = 0.f;
#pragma unroll
    for (int h = 0; h < HEADS; h++) v += ar[h * 64 + c] / dr[h];
    out[i] = 0.25f * v + bias2[c];
}

// ---------------- host launcher ----------------
extern "C" void kernel_launch(void* const* d_in, const int* in_sizes, int n_in,
                              void* d_out, int out_size) {
    const float* x        = (const float*)d_in[0];
    const int*   ei       = (const int*)d_in[1];      // int32 (JAX x64 disabled)
    const float* gamma1   = (const float*)d_in[2];
    const float* beta1    = (const float*)d_in[3];
    const float* W1       = (const float*)d_in[4];
    const float* att_src1 = (const float*)d_in[5];
    const float* att_dst1 = (const float*)d_in[6];
    const float* bias1    = (const float*)d_in[7];
    const float* gamma2   = (const float*)d_in[8];
    const float* beta2    = (const float*)d_in[9];
    const float* W2       = (const float*)d_in[10];
    const float* att_src2 = (const float*)d_in[11];
    const float* att_dst2 = (const float*)d_in[12];
    const float* bias2    = (const float*)d_in[13];

    int n = in_sizes[0] / INDIM;
    int E = in_sizes[1] / 2;
    const int* srcp = ei;
    const int* dstp = ei + E;
    float* out = (float*)d_out;

    float *p_hl, *p_h2, *p_agg, *p_denom, *p_sums, *p_scale, *p_rowbias;
    cudaGetSymbolAddress((void**)&p_hl,      g_hl);
    cudaGetSymbolAddress((void**)&p_h2,      g_h2);
    cudaGetSymbolAddress((void**)&p_agg,     g_agg);
    cudaGetSymbolAddress((void**)&p_denom,   g_denom);
    cudaGetSymbolAddress((void**)&p_sums,    g_sums);
    cudaGetSymbolAddress((void**)&p_scale,   g_scale);
    cudaGetSymbolAddress((void**)&p_rowbias, g_rowbias);

    int Et = E + n;
    int featElems = n * HH;
    dim3 gemmGrid(2, (n + 127) / 128);

    // ---- BN1 stats (folded into GEMM1 via colscale+rowbias) ----
    k_clear<<<2, 256>>>(p_sums, 512);
    k_colstats<<<512, INDIM>>>(x, n, INDIM, p_sums, p_sums + 256);
    k_bnfinal<<<1, INDIM>>>(gamma1, beta1, INDIM, n, 1);
    k_rowbias<<<1, HH>>>(W1, INDIM);

    // ---- GAT1 ----
    k_prepw<<<(256 * INDIM + 255) / 256, 256>>>(W1, INDIM, p_scale);
    k_mmagemm<<<gemmGrid, 256>>>(x, p_hl, n, INDIM, p_rowbias);
    k_attn<<<(n * 32 + 255) / 256, 256>>>(p_hl, att_src1, att_dst1, n);
    k_clear<<<(n * HEADS + 255) / 256, 256>>>(p_denom, n * HEADS);
    k_clear<<<(featElems + 255) / 256, 256>>>(p_agg, featElems);
    k_edgeagg<<<(Et * 32 + 255) / 256, 256>>>(srcp, dstp, E, n);
    k_final1<<<(featElems + 255) / 256, 256>>>(bias1, n);

    // ---- BN2 + ReLU ----
    k_clear<<<2, 256>>>(p_sums, 512);
    k_colstats<<<512, HH>>>(p_agg, n, HH, p_sums, p_sums + 256);
    k_bnfinal<<<1, HH>>>(gamma2, beta2, HH, n, 0);
    k_bnrelu<<<(featElems + 255) / 256, 256>>>(beta2, n);

    // ---- GAT2 ----
    k_prepw<<<(256 * HH + 255) / 256, 256>>>(W2, HH, nullptr);
    k_mmagemm<<<gemmGrid, 256>>>(p_h2, p_hl, n, HH, nullptr);
    k_attn<<<(n * 32 + 255) / 256, 256>>>(p_hl, att_src2, att_dst2, n);
    k_clear<<<(n * HEADS + 255) / 256, 256>>>(p_denom, n * HEADS);
    k_clear<<<(featElems + 255) / 256, 256>>>(p_agg, featElems);
    k_edgeagg<<<(Et * 32 + 255) / 256, 256>>>(srcp, dstp, E, n);
    k_final2<<<(n * HID + 255) / 256, 256>>>(bias2, out, n);
}

// round 8
// speedup vs baseline: 2.3997x; 1.9076x over previous
#include <cuda_runtime.h>
#include <cuda_bf16.h>
#include <cstdint>

#define NODES   50000
#define MAXE    800000
#define INDIM   128
#define HH      256     // HEADS*HIDDEN
#define HEADS   4
#define HID     64
#define EPSV    1e-5f
#define NEG     0.2f

// ---------------- PTX helpers (base sm_103-safe: ldmatrix + mma.sync only) ----------------
__device__ __forceinline__ uint32_t smem_to_u32(const void* p) {
    uint32_t a;
    asm("{ .reg .u64 t; cvta.to.shared.u64 t, %1; cvt.u32.u64 %0, t; }" : "=r"(a) : "l"(p));
    return a;
}
#define LDSM_X4(r0, r1, r2, r3, addr) \
    asm volatile("ldmatrix.sync.aligned.m8n8.x4.shared.b16 {%0,%1,%2,%3}, [%4];" \
        : "=r"(r0), "=r"(r1), "=r"(r2), "=r"(r3) : "r"(addr))
#define MMA_BF16(d, a, b) \
    asm volatile("mma.sync.aligned.m16n8k16.row.col.f32.bf16.bf16.f32 " \
        "{%0,%1,%2,%3}, {%4,%5,%6,%7}, {%8,%9}, {%0,%1,%2,%3};" \
        : "+f"((d)[0]), "+f"((d)[1]), "+f"((d)[2]), "+f"((d)[3]) \
        : "r"((a)[0]), "r"((a)[1]), "r"((a)[2]), "r"((a)[3]), "r"((b)[0]), "r"((b)[1]))

// -------- device scratch (no allocation allowed) --------
__device__ float g_hl [NODES * HH];
__device__ float g_h2 [NODES * HH];
__device__ float g_agg[NODES * HH];
__device__ float g_asrc[NODES * HEADS];
__device__ float g_adst[NODES * HEADS];
__device__ float g_sums[512];
__device__ float g_scale[256];
__device__ float g_shift[256];
__device__ float g_mean[256];
__device__ float g_rowbias[256];
__device__ uint16_t g_Wt_hi[256 * 256];   // W^T split: bf16 hi   [n][k]
__device__ uint16_t g_Wt_lo[256 * 256];   // bf16 lo residual     [n][k]
// CSR build scratch
__device__ int g_deg[NODES];
__device__ int g_rowptr[NODES];
__device__ int g_cursor[NODES];
__device__ int g_bsums[256];
__device__ int g_csr[MAXE + NODES];

// ---------------- utility kernels ----------------
__global__ void k_clear(float* __restrict__ p, int n) {
    int i = blockIdx.x * blockDim.x + threadIdx.x;
    if (i < n) p[i] = 0.f;
}

__global__ void k_colstats(const float* __restrict__ x, int n, int C,
                           float* __restrict__ sums, float* __restrict__ sumsq) {
    int c = threadIdx.x;
    float s = 0.f, s2 = 0.f;
    for (int r = blockIdx.x; r < n; r += gridDim.x) {
        float v = x[(size_t)r * C + c];
        s += v; s2 += v * v;
    }
    atomicAdd(&sums[c], s);
    atomicAdd(&sumsq[c], s2);
}

__global__ void k_bnfinal(const float* __restrict__ gamma, const float* __restrict__ beta,
                          int C, int n, int fold) {
    int c = threadIdx.x;
    if (c >= C) return;
    float mean = g_sums[c] / (float)n;
    float var  = g_sums[256 + c] / (float)n - mean * mean;
    float sc   = rsqrtf(var + EPSV) * gamma[c];
    g_scale[c] = sc;
    if (fold) g_shift[c] = beta[c] - mean * sc;
    else      g_mean[c]  = mean;
}

// parallel rowbias: block per output column j, 128-thread reduction over k
__global__ void k_rowbias(const float* __restrict__ W, int K) {
    __shared__ float sh[128];
    int j = blockIdx.x, t = threadIdx.x;
    float s = 0.f;
    for (int k = t; k < K; k += 128) s += g_shift[k] * W[(size_t)k * HH + j];
    sh[t] = s; __syncthreads();
    for (int off = 64; off; off >>= 1) { if (t < off) sh[t] += sh[t + off]; __syncthreads(); }
    if (t == 0) g_rowbias[j] = sh[0];
}

// ---------------- W pre-transpose + split-bf16 ----------------
__device__ __forceinline__ void splitf(float x, uint16_t& h, uint16_t& l) {
    __nv_bfloat16 bh = __float2bfloat16(x);
    float r = x - __bfloat162float(bh);
    __nv_bfloat16 bl = __float2bfloat16(r);
    h = __bfloat16_as_ushort(bh);
    l = __bfloat16_as_ushort(bl);
}

__global__ void k_prepw(const float* __restrict__ W, int K, const float* __restrict__ colscale) {
    int idx = blockIdx.x * blockDim.x + threadIdx.x;   // idx = n*K + k
    if (idx >= 256 * K) return;
    int n = idx / K, k = idx - n * K;
    float v = W[(size_t)k * 256 + n];
    if (colscale) v *= colscale[k];
    uint16_t h, l;
    splitf(v, h, l);
    g_Wt_hi[idx] = h;
    g_Wt_lo[idx] = l;
}

// ---------------- HMMA GEMM (unchanged from R7) ----------------
#define SPITCH 40
__global__ __launch_bounds__(256)
void k_mmagemm(const float* __restrict__ A, float* __restrict__ C, int M, int K,
               const float* __restrict__ rowbias) {
    __shared__ __align__(16) uint16_t As_hi[128 * SPITCH];
    __shared__ __align__(16) uint16_t As_lo[128 * SPITCH];
    __shared__ __align__(16) uint16_t Bs_hi[128 * SPITCH];
    __shared__ __align__(16) uint16_t Bs_lo[128 * SPITCH];

    const int tid = threadIdx.x, lane = tid & 31, wid = tid >> 5;
    const int warpM = wid >> 1, warpN = wid & 1;
    const int rowBase = blockIdx.y * 128;
    const int colBase = blockIdx.x * 128;

    const uint32_t sAh = smem_to_u32(As_hi), sAl = smem_to_u32(As_lo);
    const uint32_t sBh = smem_to_u32(Bs_hi), sBl = smem_to_u32(Bs_lo);

    float acc[2][8][4] = {};

    for (int k0 = 0; k0 < K; k0 += 32) {
        for (int i = tid; i < 128 * 8; i += 256) {
            int r = i >> 3, q = i & 7;
            int gr = rowBase + r;
            float4 v = make_float4(0.f, 0.f, 0.f, 0.f);
            if (gr < M) v = *(const float4*)(A + (size_t)gr * K + k0 + q * 4);
            uint16_t h0, h1, h2, h3, l0, l1, l2, l3;
            splitf(v.x, h0, l0); splitf(v.y, h1, l1);
            splitf(v.z, h2, l2); splitf(v.w, h3, l3);
            int off = r * SPITCH + q * 4;
            uint32_t* ph = (uint32_t*)(As_hi + off);
            uint32_t* pl = (uint32_t*)(As_lo + off);
            ph[0] = (uint32_t)h0 | ((uint32_t)h1 << 16);
            ph[1] = (uint32_t)h2 | ((uint32_t)h3 << 16);
            pl[0] = (uint32_t)l0 | ((uint32_t)l1 << 16);
            pl[1] = (uint32_t)l2 | ((uint32_t)l3 << 16);
        }
        for (int i = tid; i < 128 * 8; i += 256) {
            int n = i >> 3, q = i & 7;
            size_t gofs = (size_t)(colBase + n) * K + k0 + q * 4;
            uint2 vh = *(const uint2*)(g_Wt_hi + gofs);
            uint2 vl = *(const uint2*)(g_Wt_lo + gofs);
            int off = n * SPITCH + q * 4;
            *(uint2*)(Bs_hi + off) = vh;
            *(uint2*)(Bs_lo + off) = vl;
        }
        __syncthreads();

#pragma unroll
        for (int s = 0; s < 2; s++) {
            uint32_t ah[2][4], al[2][4];
#pragma unroll
            for (int mt = 0; mt < 2; mt++) {
                int rA = warpM * 32 + mt * 16 + (lane & 15);
                int kA = s * 16 + ((lane & 16) ? 8 : 0);
                uint32_t byteOff = (uint32_t)(rA * SPITCH + kA) * 2;
                LDSM_X4(ah[mt][0], ah[mt][1], ah[mt][2], ah[mt][3], sAh + byteOff);
                LDSM_X4(al[mt][0], al[mt][1], al[mt][2], al[mt][3], sAl + byteOff);
            }
            uint32_t bh[8][2], bl[8][2];
#pragma unroll
            for (int p = 0; p < 4; p++) {
                int g = lane >> 3;
                int nB = warpN * 64 + p * 16 + ((g & 2) ? 8 : 0) + (lane & 7);
                int kB = s * 16 + ((g & 1) ? 8 : 0);
                uint32_t byteOff = (uint32_t)(nB * SPITCH + kB) * 2;
                LDSM_X4(bh[2*p][0], bh[2*p][1], bh[2*p+1][0], bh[2*p+1][1], sBh + byteOff);
                LDSM_X4(bl[2*p][0], bl[2*p][1], bl[2*p+1][0], bl[2*p+1][1], sBl + byteOff);
            }
#pragma unroll
            for (int mt = 0; mt < 2; mt++)
#pragma unroll
                for (int nt = 0; nt < 8; nt++) {
                    MMA_BF16(acc[mt][nt], ah[mt], bh[nt]);
                    MMA_BF16(acc[mt][nt], ah[mt], bl[nt]);
                    MMA_BF16(acc[mt][nt], al[mt], bh[nt]);
                }
        }
        __syncthreads();
    }

#pragma unroll
    for (int mt = 0; mt < 2; mt++) {
        int r0 = rowBase + warpM * 32 + mt * 16 + (lane >> 2);
#pragma unroll
        for (int half = 0; half < 2; half++) {
            int row = r0 + half * 8;
            if (row >= M) continue;
#pragma unroll
            for (int nt = 0; nt < 8; nt++) {
                int col = colBase + warpN * 64 + nt * 8 + (lane & 3) * 2;
                float v0 = acc[mt][nt][half * 2];
                float v1 = acc[mt][nt][half * 2 + 1];
                if (rowbias) { v0 += rowbias[col]; v1 += rowbias[col + 1]; }
                *(float2*)(C + (size_t)row * 256 + col) = make_float2(v0, v1);
            }
        }
    }
}

// ---------------- attention scores: warp per node ----------------
__global__ void k_attn(const float* __restrict__ hl, const float* __restrict__ atts,
                       const float* __restrict__ attd, int n) {
    int w = (blockIdx.x * blockDim.x + threadIdx.x) >> 5;
    int lane = threadIdx.x & 31;
    if (w >= n) return;
    const float* row = hl + (size_t)w * HH;
    float ss[HEADS] = {}, dd[HEADS] = {};
#pragma unroll
    for (int h = 0; h < HEADS; h++) {
#pragma unroll
        for (int j = 0; j < 2; j++) {
            int c = h * 64 + j * 32 + lane;
            float v = row[c];
            ss[h] += v * atts[c];
            dd[h] += v * attd[c];
        }
    }
#pragma unroll
    for (int off = 16; off; off >>= 1) {
#pragma unroll
        for (int h = 0; h < HEADS; h++) {
            ss[h] += __shfl_xor_sync(0xffffffffu, ss[h], off);
            dd[h] += __shfl_xor_sync(0xffffffffu, dd[h], off);
        }
    }
    if (lane == 0) {
#pragma unroll
        for (int h = 0; h < HEADS; h++) {
            g_asrc[w * HEADS + h] = ss[h];
            g_adst[w * HEADS + h] = dd[h];
        }
    }
}

// ---------------- CSR build ----------------
__global__ void k_deginit(int n) {           // deg = 1 (self loop)
    int i = blockIdx.x * blockDim.x + threadIdx.x;
    if (i < n) g_deg[i] = 1;
}
__global__ void k_hist(const int* __restrict__ dstp, int E) {
    int i = blockIdx.x * blockDim.x + threadIdx.x;
    if (i < E) atomicAdd(&g_deg[dstp[i]], 1);
}
__global__ void k_scan1(int n) {
    __shared__ int sh[256];
    int tid = threadIdx.x;
    int i = blockIdx.x * 256 + tid;
    int v = (i < n) ? g_deg[i] : 0;
    sh[tid] = v; __syncthreads();
    for (int off = 1; off < 256; off <<= 1) {
        int t = (tid >= off) ? sh[tid - off] : 0;
        __syncthreads();
        sh[tid] += t;
        __syncthreads();
    }
    if (i < n) g_rowptr[i] = sh[tid] - v;   // exclusive within block
    if (tid == 255) g_bsums[blockIdx.x] = sh[255];
}
__global__ void k_scan2(int nb) {
    __shared__ int sh[256];
    int tid = threadIdx.x;
    int v = (tid < nb) ? g_bsums[tid] : 0;
    sh[tid] = v; __syncthreads();
    for (int off = 1; off < 256; off <<= 1) {
        int t = (tid >= off) ? sh[tid - off] : 0;
        __syncthreads();
        sh[tid] += t;
        __syncthreads();
    }
    if (tid < nb) g_bsums[tid] = sh[tid] - v;  // exclusive block offsets
}
__global__ void k_scan3(int n) {
    int i = blockIdx.x * 256 + threadIdx.x;
    if (i < n) {
        int r = g_rowptr[i] + g_bsums[blockIdx.x];
        g_rowptr[i] = r;
        g_cursor[i] = r;
    }
}
__global__ void k_scatter(const int* __restrict__ srcp, const int* __restrict__ dstp,
                          int E, int n) {
    int i = blockIdx.x * blockDim.x + threadIdx.x;
    int Et = E + n;
    if (i >= Et) return;
    int s, d;
    if (i < E) { s = srcp[i]; d = dstp[i]; }
    else       { s = d = i - E; }
    int pos = atomicAdd(&g_cursor[d], 1);
    g_csr[pos] = s;
}

// ---------------- gather aggregation: warp per dst node ----------------
// LAYER=1: writes g_agg[d][256] = softmax-weighted sum / denom + bias (concat)
// LAYER=2: writes out[d][64]    = mean over heads + bias
template <int LAYER>
__global__ void k_gather(const float* __restrict__ bias, float* __restrict__ out, int n) {
    int d = (blockIdx.x * blockDim.x + threadIdx.x) >> 5;
    int lane = threadIdx.x & 31;
    if (d >= n) return;

    float adv = 0.f;
    if (lane < HEADS) adv = g_adst[d * HEADS + lane];

    int e   = g_rowptr[d];
    int end = g_cursor[d];     // cursor == rowptr + deg after scatter

    float acc[8] = {};
    float den = 0.f;
    for (; e < end; e++) {
        int s = g_csr[e];
        float wl = 0.f;
        if (lane < HEADS) {
            float a = g_asrc[s * HEADS + lane] + adv;
            a = (a > 0.f) ? a : NEG * a;
            wl = __expf(a);
            den += wl;
        }
        const float* hr = g_hl + (size_t)s * HH;
#pragma unroll
        for (int h = 0; h < HEADS; h++) {
            float wh = __shfl_sync(0xffffffffu, wl, h);
            acc[2*h]   += wh * hr[h * 64 + lane];
            acc[2*h+1] += wh * hr[h * 64 + 32 + lane];
        }
    }
    float dv[4];
#pragma unroll
    for (int h = 0; h < HEADS; h++) dv[h] = __shfl_sync(0xffffffffu, den, h);

    if (LAYER == 1) {
        float* orow = g_agg + (size_t)d * HH;
#pragma unroll
        for (int h = 0; h < HEADS; h++) {
            int c0 = h * 64 + lane;
            orow[c0]      = acc[2*h]   / dv[h] + bias[c0];
            orow[c0 + 32] = acc[2*h+1] / dv[h] + bias[c0 + 32];
        }
    } else {
        float v0 = 0.f, v1 = 0.f;
#pragma unroll
        for (int h = 0; h < HEADS; h++) {
            v0 += acc[2*h]   / dv[h];
            v1 += acc[2*h+1] / dv[h];
        }
        out[d * HID + lane]      = 0.25f * v0 + bias[lane];
        out[d * HID + lane + 32] = 0.25f * v1 + bias[lane + 32];
    }
}

// BN2 normalize + ReLU -> g_h2
__global__ void k_bnrelu(const float* __restrict__ beta, int n) {
    size_t i = (size_t)blockIdx.x * blockDim.x + threadIdx.x;
    if (i >= (size_t)n * HH) return;
    int c = (int)(i & 255);
    float v = (g_agg[i] - g_mean[c]) * g_scale[c] + beta[c];
    g_h2[i] = (v > 0.f) ? v : 0.f;
}

// ---------------- host launcher ----------------
extern "C" void kernel_launch(void* const* d_in, const int* in_sizes, int n_in,
                              void* d_out, int out_size) {
    const float* x        = (const float*)d_in[0];
    const int*   ei       = (const int*)d_in[1];      // int32 (JAX x64 disabled)
    const float* gamma1   = (const float*)d_in[2];
    const float* beta1    = (const float*)d_in[3];
    const float* W1       = (const float*)d_in[4];
    const float* att_src1 = (const float*)d_in[5];
    const float* att_dst1 = (const float*)d_in[6];
    const float* bias1    = (const float*)d_in[7];
    const float* gamma2   = (const float*)d_in[8];
    const float* beta2    = (const float*)d_in[9];
    const float* W2       = (const float*)d_in[10];
    const float* att_src2 = (const float*)d_in[11];
    const float* att_dst2 = (const float*)d_in[12];
    const float* bias2    = (const float*)d_in[13];

    int n = in_sizes[0] / INDIM;
    int E = in_sizes[1] / 2;
    const int* srcp = ei;
    const int* dstp = ei + E;
    float* out = (float*)d_out;

    float *p_hl, *p_h2, *p_agg, *p_sums, *p_scale, *p_rowbias;
    cudaGetSymbolAddress((void**)&p_hl,      g_hl);
    cudaGetSymbolAddress((void**)&p_h2,      g_h2);
    cudaGetSymbolAddress((void**)&p_agg,     g_agg);
    cudaGetSymbolAddress((void**)&p_sums,    g_sums);
    cudaGetSymbolAddress((void**)&p_scale,   g_scale);
    cudaGetSymbolAddress((void**)&p_rowbias, g_rowbias);

    int Et = E + n;
    int featElems = n * HH;
    int scanBlocks = (n + 255) / 256;
    dim3 gemmGrid(2, (n + 127) / 128);

    // ---- CSR build (shared by both layers) ----
    k_deginit<<<scanBlocks, 256>>>(n);
    k_hist<<<(E + 255) / 256, 256>>>(dstp, E);
    k_scan1<<<scanBlocks, 256>>>(n);
    k_scan2<<<1, 256>>>(scanBlocks);
    k_scan3<<<scanBlocks, 256>>>(n);
    k_scatter<<<(Et + 255) / 256, 256>>>(srcp, dstp, E, n);

    // ---- BN1 stats (folded into GEMM1 via colscale+rowbias) ----
    k_clear<<<2, 256>>>(p_sums, 512);
    k_colstats<<<512, INDIM>>>(x, n, INDIM, p_sums, p_sums + 256);
    k_bnfinal<<<1, INDIM>>>(gamma1, beta1, INDIM, n, 1);
    k_rowbias<<<HH, 128>>>(W1, INDIM);

    // ---- GAT1 ----
    k_prepw<<<(256 * INDIM + 255) / 256, 256>>>(W1, INDIM, p_scale);
    k_mmagemm<<<gemmGrid, 256>>>(x, p_hl, n, INDIM, p_rowbias);
    k_attn<<<(n * 32 + 255) / 256, 256>>>(p_hl, att_src1, att_dst1, n);
    k_gather<1><<<(n * 32 + 255) / 256, 256>>>(bias1, nullptr, n);

    // ---- BN2 + ReLU ----
    k_clear<<<2, 256>>>(p_sums, 512);
    k_colstats<<<512, HH>>>(p_agg, n, HH, p_sums, p_sums + 256);
    k_bnfinal<<<1, HH>>>(gamma2, beta2, HH, n, 0);
    k_bnrelu<<<(featElems + 255) / 256, 256>>>(beta2, n);

    // ---- GAT2 ----
    k_prepw<<<(256 * HH + 255) / 256, 256>>>(W2, HH, nullptr);
    k_mmagemm<<<gemmGrid, 256>>>(p_h2, p_hl, n, HH, nullptr);
    k_attn<<<(n * 32 + 255) / 256, 256>>>(p_hl, att_src2, att_dst2, n);
    k_gather<2><<<(n * 32 + 255) / 256, 256>>>(bias2, out, n);
}